// round 13
// baseline (speedup 1.0000x reference)
#include <cuda_runtime.h>

#define PSZ 16
#define HW 224
#define NP 14          // patches per spatial dim (224/16)
#define S4 56          // float4 per strip row
#define PROWS 5        // padded smem row stride per patch (float4 units)
#define PSTRIDE 80     // per-patch smem size: 16 rows * 5 (float4)
#define STRIP4 896     // float4 per strip
#define NSTRIPS (256 * 3 * NP)   // 10752 work units
#define GRID 1036      // 148 SMs x 7 resident blocks -> exactly one wave

__global__ __launch_bounds__(224) void patch_rotate_kernel(
    const float* __restrict__ x,
    const void* __restrict__ mask_raw,
    float* __restrict__ out)
{
    // per-warp private regions: 7 warps x 2 patches x 80 float4 = 17.5 KB
    __shared__ float4 tile[7 * 2 * PSTRIDE];

    const int t    = threadIdx.x;          // 0..223
    const int lane = t & 31;

    // thread -> (patch, 4x4 sub-block): 16 consecutive lanes own one patch
    const int wi = t >> 4;                 // 0..13 patch column
    const int p  = (t >> 4) & 1;           // patch slot within warp
    const int R  = (t >> 2) & 3;           // sub-block row group
    const int J  = t & 3;                  // sub-block fcol within patch
    const int fcol = 4 * wi + J;
    const int jbit = (J & 2);
    const int rbit = (R & 2);

    float4* wtile = tile + (t >> 5) * (2 * PSTRIDE);   // this warp's region

    // dtype probe (once): int32 bool -> every word 0/1; uint8 -> word>1 w.p. 7/8. P(miss)=8^-32.
    const unsigned pv = ((const unsigned int*)mask_raw)[lane];
    const bool is_int32 = (__ballot_sync(0xFFFFFFFFu, pv > 1u) == 0u);

    // persistent grid-stride loop: one resident wave, no wave transitions
    for (int u = blockIdx.x; u < NSTRIPS; u += GRID) {
        const int hi = u % NP;             // patch-row
        const int bc = u / NP;             // b*3 + c
        const int b  = bc / 3;

        const unsigned base4 = (unsigned)bc * (HW * HW / 4) + (unsigned)hi * STRIP4;
        const float4* src4 = (const float4*)x + base4;
        float4*       dst4 = (float4*)out     + base4;

        // front-batched coalesced LDG.128 (4 x 128B lines per warp per k)
        float4 v[4];
        #pragma unroll
        for (int k = 0; k < 4; k++)
            v[k] = src4[(unsigned)(4*R + k) * S4 + fcol];

        const int midx = b * (NP*NP) + wi * NP + hi;                      // mask[b, wi, hi]
        bool mm;
        if (is_int32) mm = (((const int*)mask_raw)[midx] != 0);
        else          mm = (((const unsigned char*)mask_raw)[midx] != 0);

        // register 4x4 transpose + swizzled vector STS (masked patches only, warp-local)
        // phys(row, fc) = row*5 + (fc ^ ((row>>2)&2))
        if (mm) {
            #pragma unroll
            for (int e = 0; e < 4; e++) {
                int row = 4*J + e;
                int adr = p * PSTRIDE + row * PROWS + (R ^ jbit);
                float4 w;
                w.x = (&v[0].x)[e]; w.y = (&v[1].x)[e];
                w.z = (&v[2].x)[e]; w.w = (&v[3].x)[e];
                wtile[adr] = w;
            }
        }
        __syncwarp();

        // gather + coalesced STG.128
        #pragma unroll
        for (int k = 0; k < 4; k++) {
            float4 o = v[k];
            if (mm) {
                int row = 4*R + k;
                o = wtile[p * PSTRIDE + row * PROWS + (J ^ rbit)];
            }
            dst4[(unsigned)(4*R + k) * S4 + fcol] = o;
        }
        __syncwarp();   // WAR: next iteration's STS must not clobber live LDS
    }
}

extern "C" void kernel_launch(void* const* d_in, const int* in_sizes, int n_in,
                              void* d_out, int out_size)
{
    const float* x    = (const float*)d_in[0];
    const void*  mask = d_in[1];
    float*       out  = (float*)d_out;

    patch_rotate_kernel<<<GRID, 224>>>(x, mask, out);
}

// round 14
// speedup vs baseline: 1.2128x; 1.2128x over previous
#include <cuda_runtime.h>

#define PSZ 16
#define HW 224
#define NP 14          // patches per spatial dim (224/16)
#define S4 56          // float4 per strip row
#define PROWS 5        // padded smem row stride per patch (float4 units)
#define PSTRIDE 80     // per-patch smem size: 16 rows * 5 (float4)

__global__ __launch_bounds__(224) void patch_rotate_kernel(
    const float* __restrict__ x,
    const void* __restrict__ mask_raw,
    float* __restrict__ out)
{
    // per-warp private regions: 7 warps x 2 patches x 80 float4 = 17.5 KB
    __shared__ float4 tile[7 * 2 * PSTRIDE];

    const int bid = blockIdx.x;
    const int hi  = bid % NP;              // patch-row index
    const int bc  = bid / NP;              // b*3 + c
    const int b   = bc / 3;
    const int t   = threadIdx.x;           // 0..223
    const int lane = t & 31;

    // thread -> (patch, 4x4 sub-block): 16 consecutive lanes own one patch
    const int wi = t >> 4;                 // 0..13 patch column
    const int p  = (t >> 4) & 1;           // patch slot within warp
    const int R  = (t >> 2) & 3;           // sub-block row group (rows 4R..4R+3)
    const int J  = t & 3;                  // sub-block fcol within patch
    const int fcol = 4 * wi + J;

    float4* wtile = tile + (t >> 5) * (2 * PSTRIDE);   // this warp's region

    const float4* src4 = (const float4*)(x   + (size_t)bc * (HW*HW) + (size_t)hi * (PSZ*HW));
    float4*       dst4 = (float4*)      (out + (size_t)bc * (HW*HW) + (size_t)hi * (PSZ*HW));

    // ---- issue all independent loads up front ----
    float4 v[4];
    #pragma unroll
    for (int k = 0; k < 4; k++)
        v[k] = src4[(4*R + k) * S4 + fcol];

    // dtype probe: int32 bool buffer -> every word is 0/1; uint8 -> word>1 w.p. 7/8.
    // 32 words/warp: P(uint8 misdetected) = 8^-32.
    const unsigned pv = ((const unsigned int*)mask_raw)[lane];
    const int midx = b * (NP*NP) + wi * NP + hi;                      // mask[b, wi, hi]
    const unsigned char m8 = ((const unsigned char*)mask_raw)[midx];  // in-bounds either way

    const bool is_int32 = (__ballot_sync(0xFFFFFFFFu, pv > 1u) == 0u);
    bool mm;
    if (is_int32) mm = (((const int*)mask_raw)[midx] != 0);  // predicated: no OOB if uint8
    else          mm = (m8 != 0);

    // ---- register 4x4 transpose + vector STS (masked patches only, warp-local) ----
    // swizzled per-patch layout: phys(row, fc) = row*5 + (fc ^ ((row>>2)&2))
    if (mm) {
        const int jbit = (J & 2);
        #pragma unroll
        for (int e = 0; e < 4; e++) {
            int row = 4*J + e;                         // logical transposed row
            int adr = p * PSTRIDE + row * PROWS + (R ^ jbit);
            float4 w;
            w.x = (&v[0].x)[e]; w.y = (&v[1].x)[e]; w.z = (&v[2].x)[e]; w.w = (&v[3].x)[e];
            wtile[adr] = w;
        }
    }
    __syncwarp();

    // ---- gather + store: masked -> swizzled LDS.128, unmasked -> register passthrough ----
    const int rbit = (R & 2);
    #pragma unroll
    for (int k = 0; k < 4; k++) {
        float4 o = v[k];
        if (mm) {
            int row = 4*R + k;
            o = wtile[p * PSTRIDE + row * PROWS + (J ^ rbit)];
        }
        dst4[(4*R + k) * S4 + fcol] = o;
    }
}

extern "C" void kernel_launch(void* const* d_in, const int* in_sizes, int n_in,
                              void* d_out, int out_size)
{
    const float* x    = (const float*)d_in[0];
    const void*  mask = d_in[1];
    float*       out  = (float*)d_out;

    // one block per (b, c, patch-row) strip = 256*3*14 = 10752 blocks
    patch_rotate_kernel<<<10752, 224>>>(x, mask, out);
}